// round 12
// baseline (speedup 1.0000x reference)
#include <cuda_runtime.h>

#define Hh 51
#define H4 204
#define TT 1024
#define NCTA 128
#define NTHR 832   // warps 0-12: L1 (A) + head in warp-12 hi lanes; warps 13-25: L2 (B)

// ---- shared memory (float offsets) ----
// Weights: [204][56] rows (cols 51..55 zero). stride 56 floats = 14 chunks ->
//   4j x 2ch chunk residues {0,6,4,2}+{7,5,3,1}: conflict-free.
// W2h at +4 floats (16B) past 2*11424 -> +1 chunk vs W2i: B's dual-matrix loads conflict-free.
// h arrays: [2 buf][480] gapped k-pair layout: pair p at POFF(p)=p*16+(p>=14?16:0);
//   buf stride 480 (1920B % 128 == 0, bank-neutral); OFF_H2-OFF_H1=976 (3904B % 128 == 64).
#define OFF_W1   0
#define OFF_W2I  11424
#define OFF_W2H  22852
#define OFF_WLIN 34276
#define OFF_X    34328
#define OFF_H1   42528
#define OFF_H2   43504
#define SMEM_FLOATS 44464
#define SMEM_BYTES  (SMEM_FLOATS * 4)

#define POFF(p) ((p) * 16 + ((p) >= 14 ? 16 : 0))

typedef unsigned long long u64;

__device__ __forceinline__ u64 splat2(float w) {
    unsigned int wi = __float_as_uint(w);
    u64 r;
    asm("mov.b64 %0, {%1, %1};" : "=l"(r) : "r"(wi));
    return r;
}
__device__ __forceinline__ void ffma2(u64& d, u64 a, u64 b) {
    asm("fma.rn.f32x2 %0, %1, %2, %0;" : "+l"(d) : "l"(a), "l"(b));
}
__device__ __forceinline__ float2 u2f(u64 v) {
    float2 f;
    asm("mov.b64 {%0, %1}, %2;" : "=f"(f.x), "=f"(f.y) : "l"(v));
    return f;
}
__device__ __forceinline__ u64 f2u(float x, float y) {
    u64 v;
    asm("mov.b64 %0, {%1, %2};" : "=l"(v) : "f"(x), "f"(y));
    return v;
}
__device__ __forceinline__ float sigf(float x) {
    return __fdividef(1.0f, 1.0f + __expf(-x));
}
__device__ __forceinline__ float tanhfast(float x) {
    return 1.0f - __fdividef(2.0f, __expf(2.0f * x) + 1.0f);
}
__device__ __forceinline__ void bar_arrive(int id) {
    asm volatile("bar.arrive %0, %1;" :: "r"(id), "r"(NTHR) : "memory");
}
__device__ __forceinline__ void bar_wait(int id) {
    asm volatile("bar.sync %0, %1;" :: "r"(id), "r"(NTHR) : "memory");
}

// one quad: 4 weight float4 (one per gate row) x 2 h-pair LDS -> 16 FFMA2
#define QUAD(wc, hoff) { \
    const float4 wi = *(const float4*)(wp0 + (wc)); \
    const float4 wf = *(const float4*)(wp1 + (wc)); \
    const float4 wg = *(const float4*)(wp2 + (wc)); \
    const float4 wo = *(const float4*)(wp3 + (wc)); \
    const ulonglong2 v0 = *(const ulonglong2*)(hbase + (hoff)); \
    const ulonglong2 v1 = *(const ulonglong2*)(hbase + (hoff) + 16); \
    ffma2(ai, splat2(wi.x), v0.x); ffma2(ai, splat2(wi.y), v0.y); \
    ffma2(ai, splat2(wi.z), v1.x); ffma2(ai, splat2(wi.w), v1.y); \
    ffma2(af, splat2(wf.x), v0.x); ffma2(af, splat2(wf.y), v0.y); \
    ffma2(af, splat2(wf.z), v1.x); ffma2(af, splat2(wf.w), v1.y); \
    ffma2(ag, splat2(wg.x), v0.x); ffma2(ag, splat2(wg.y), v0.y); \
    ffma2(ag, splat2(wg.z), v1.x); ffma2(ag, splat2(wg.w), v1.y); \
    ffma2(ao, splat2(wo.x), v0.x); ffma2(ao, splat2(wo.y), v0.y); \
    ffma2(ao, splat2(wo.z), v1.x); ffma2(ao, splat2(wo.w), v1.y); }

#define REDUCE4(msk) { \
    u64 x_; \
    x_ = __shfl_xor_sync((msk), ai, 4); \
    asm("add.rn.f32x2 %0, %0, %1;" : "+l"(ai) : "l"(x_)); \
    x_ = __shfl_xor_sync((msk), af, 4); \
    asm("add.rn.f32x2 %0, %0, %1;" : "+l"(af) : "l"(x_)); \
    x_ = __shfl_xor_sync((msk), ag, 4); \
    asm("add.rn.f32x2 %0, %0, %1;" : "+l"(ag) : "l"(x_)); \
    x_ = __shfl_xor_sync((msk), ao, 4); \
    asm("add.rn.f32x2 %0, %0, %1;" : "+l"(ao) : "l"(x_)); }

#define UPDATE(cvar, hout) { \
    const float2 gi = u2f(ai), gf = u2f(af), gg = u2f(ag), go = u2f(ao); \
    const float i0 = sigf(gi.x), f0 = sigf(gf.x), g0 = tanhfast(gg.x), o0 = sigf(go.x); \
    const float i1 = sigf(gi.y), f1 = sigf(gf.y), g1 = tanhfast(gg.y), o1 = sigf(go.y); \
    cvar.x = f0 * cvar.x + i0 * g0; \
    cvar.y = f1 * cvar.y + i1 * g1; \
    hout = f2u(o0 * tanhfast(cvar.x), o1 * tanhfast(cvar.y)); }

__global__ __launch_bounds__(NTHR, 1)
void lstm_seq_kernel(const float* __restrict__ input,
                     const float* __restrict__ W_ih1, const float* __restrict__ W_hh1,
                     const float* __restrict__ b_ih1, const float* __restrict__ b_hh1,
                     const float* __restrict__ W_ih2, const float* __restrict__ W_hh2,
                     const float* __restrict__ b_ih2, const float* __restrict__ b_hh2,
                     const float* __restrict__ W_lin, const float* __restrict__ b_lin,
                     float* __restrict__ out)
{
    extern __shared__ float sm[];
    float* sW1   = sm + OFF_W1;
    float* sW2i  = sm + OFF_W2I;
    float* sW2h  = sm + OFF_W2H;
    float* sWlin = sm + OFF_WLIN;
    float* sX    = sm + OFF_X;
    float* sH1   = sm + OFF_H1;   // [2][480]
    float* sH2   = sm + OFF_H2;   // [2][480]

    const int tid = threadIdx.x;
    const int b0  = blockIdx.x * 8;

    // ---------------- staging ----------------
    for (int i = tid; i < OFF_WLIN; i += NTHR) sm[i] = 0.0f;    // zero all weight rows (incl pads)
    for (int i = tid; i < 1936; i += NTHR) sH1[i] = 0.0f;       // zero h1+h2 (both bufs + gaps)
    __syncthreads();
    for (int i = tid; i < H4 * Hh; i += NTHR) {
        const int r = i / Hh, k = i % Hh;
        sW1[r * 56 + k]  = W_hh1[i];
        sW2i[r * 56 + k] = W_ih2[i];
        sW2h[r * 56 + k] = W_hh2[i];
    }
    if (tid < 52) sWlin[tid] = (tid < Hh) ? W_lin[tid] : 0.0f;
    for (int i = tid; i < 8 * TT; i += NTHR) {
        const int b = i >> 10, t = i & 1023;
        sX[t * 8 + b] = input[b0 * TT + i];
    }

    // ---------------- roles ----------------
    const bool isA = (tid < 416);
    const int  gt  = isA ? tid : (tid - 416);  // 0..415
    const int  bp  = gt & 3;
    const int  ch  = (gt >> 2) & 1;
    const int  jr  = gt >> 3;                  // 0..51
    const int  j   = (jr < Hh) ? jr : (Hh - 1);
    const bool valid = (jr < Hh);
    // head: A warp 12 lanes 24..31 (jr == 51)
    const bool ishead = isA && !valid;
    const int  hbb = gt - 408;                 // 0..7 for head lanes
    // shuffle masks: A warp 12 gate lanes exclude head lanes
    const unsigned amask = (isA && (tid >> 5) == 12) ? 0x00FFFFFFu : 0xFFFFFFFFu;

    const int ri = j, rf = Hh + j, rg = 2 * Hh + j, ro = 3 * Hh + j;
    u64 sd_i = 0, sd_f = 0, sd_g = 0, sd_o = 0;   // acc seeds (ch0 carries bias)
    u64 wxi = 0, wxf = 0, wxg = 0, wxo = 0;
    const float *wp0, *wp1, *wp2, *wp3;
    if (isA) {
        const int cb = ch * 28;                   // k-half column base
        wp0 = sW1 + ri * 56 + cb; wp1 = sW1 + rf * 56 + cb;
        wp2 = sW1 + rg * 56 + cb; wp3 = sW1 + ro * 56 + cb;
        if (ch == 0) {
            sd_i = splat2(b_ih1[ri] + b_hh1[ri]);
            sd_f = splat2(b_ih1[rf] + b_hh1[rf]);
            sd_g = splat2(b_ih1[rg] + b_hh1[rg]);
            sd_o = splat2(b_ih1[ro] + b_hh1[ro]);
            wxi = splat2(W_ih1[ri]); wxf = splat2(W_ih1[rf]);
            wxg = splat2(W_ih1[rg]); wxo = splat2(W_ih1[ro]);
        }
    } else {
        const float* wb = ch ? sW2h : sW2i;       // ch0 = ih2 (over h1), ch1 = hh2 (over h2)
        wp0 = wb + ri * 56; wp1 = wb + rf * 56;
        wp2 = wb + rg * 56; wp3 = wb + ro * 56;
        if (ch == 0) {
            sd_i = splat2(b_ih2[ri] + b_hh2[ri]);
            sd_f = splat2(b_ih2[rf] + b_hh2[rf]);
            sd_g = splat2(b_ih2[rg] + b_hh2[rg]);
            sd_o = splat2(b_ih2[ro] + b_hh2[ro]);
        }
    }
    // store offset (ch0 stores)
    const int pj  = j >> 1;
    const int sto = POFF(pj) + bp * 4 + (j & 1) * 2;
    // A h-read base offset within buf: ch half + bp
    const int hA = ch * 240 + bp * 4;

    float2 cc = make_float2(0.0f, 0.0f);
    const float blin = b_lin[0];

    __syncthreads();

    // ---------------- prologue: A computes h1(0) into buf 0 ----------------
    if (isA) {
        if (!ishead) {
            u64 ai = sd_i, af = sd_f, ag = sd_g, ao = sd_o;
            if (ch == 0) {
                const u64 xv = *(const u64*)(sX + bp * 2);
                ffma2(ai, wxi, xv); ffma2(af, wxf, xv);
                ffma2(ag, wxg, xv); ffma2(ao, wxo, xv);
            }
            const float* hbase = sH1 + 480 + hA;   // buf 1: zeros
            #pragma unroll
            for (int s = 0; s < 7; ++s) QUAD(s * 4, s * 32)
            REDUCE4(amask)
            u64 hnew;
            UPDATE(cc, hnew);
            if (valid && ch == 0) *(u64*)(sH1 + sto) = hnew;
        }
        bar_arrive(1);                              // h1(0) ready
    } else {
        bar_arrive(2);
    }

    // ---------------- time loop ----------------
    for (int t = 0; t < TT; ++t) {
        const int pt = t & 1, pn = pt ^ 1;

        if (isA) {
            bar_wait(2);                            // B(t-1) done
            if (!ishead) {
                if (t < TT - 1) {
                    // h1(t+1): x(t+1) + W_hh1 . h1(t)[pt] -> buf pn
                    u64 ai = sd_i, af = sd_f, ag = sd_g, ao = sd_o;
                    if (ch == 0) {
                        const u64 xv = *(const u64*)(sX + (t + 1) * 8 + bp * 2);
                        ffma2(ai, wxi, xv); ffma2(af, wxf, xv);
                        ffma2(ag, wxg, xv); ffma2(ao, wxo, xv);
                    }
                    const float* hbase = sH1 + pt * 480 + hA;
                    #pragma unroll
                    for (int s = 0; s < 7; ++s) QUAD(s * 4, s * 32)
                    REDUCE4(amask)
                    u64 hnew;
                    UPDATE(cc, hnew);
                    if (valid && ch == 0) *(u64*)(sH1 + pn * 480 + sto) = hnew;
                }
            } else if (t >= 1) {
                // head(t-1): reads h2(t-1)[pn]
                const float* h2r = sH2 + pn * 480;
                float p = 0.0f;
                #pragma unroll
                for (int k = 0; k < Hh; ++k)
                    p = fmaf(sWlin[k],
                             h2r[POFF(k >> 1) + (hbb >> 1) * 4 + (k & 1) * 2 + (hbb & 1)],
                             p);
                out[(b0 + hbb) * TT + (t - 1)] = p + blin;
            }
            if (t < TT - 1) bar_arrive(1);          // h1(t+1) ready
        } else {
            bar_wait(1);                            // h1(t) ready
            // L2 cell(t): ch0 = W_ih2 . h1(t)[pt]; ch1 = W_hh2 . h2(t-1)[pn]
            u64 ai = sd_i, af = sd_f, ag = sd_g, ao = sd_o;
            const float* hbase = (ch ? (sH2 + pn * 480) : (sH1 + pt * 480)) + bp * 4;
            #pragma unroll
            for (int s = 0; s < 13; ++s) QUAD(s * 4, s * 32 + ((s >= 7) ? 16 : 0))
            REDUCE4(0xFFFFFFFFu)
            u64 hnew;
            UPDATE(cc, hnew);
            if (valid && ch == 0) *(u64*)(sH2 + pt * 480 + sto) = hnew;
            bar_arrive(2);
        }
    }

    // ---------------- epilogue: head(TT-1) ----------------
    if (isA) {
        bar_wait(2);
        if (ishead) {
            const float* h2r = sH2 + ((TT - 1) & 1) * 480;
            float p = 0.0f;
            #pragma unroll
            for (int k = 0; k < Hh; ++k)
                p = fmaf(sWlin[k],
                         h2r[POFF(k >> 1) + (hbb >> 1) * 4 + (k & 1) * 2 + (hbb & 1)],
                         p);
            out[(b0 + hbb) * TT + (TT - 1)] = p + blin;
        }
    }
}

extern "C" void kernel_launch(void* const* d_in, const int* in_sizes, int n_in,
                              void* d_out, int out_size) {
    const float* input = (const float*)d_in[0];
    const float* W_ih1 = (const float*)d_in[1];
    const float* W_hh1 = (const float*)d_in[2];
    const float* b_ih1 = (const float*)d_in[3];
    const float* b_hh1 = (const float*)d_in[4];
    const float* W_ih2 = (const float*)d_in[5];
    const float* W_hh2 = (const float*)d_in[6];
    const float* b_ih2 = (const float*)d_in[7];
    const float* b_hh2 = (const float*)d_in[8];
    const float* W_lin = (const float*)d_in[9];
    const float* b_lin = (const float*)d_in[10];
    float* out = (float*)d_out;

    cudaFuncSetAttribute(lstm_seq_kernel,
                         cudaFuncAttributeMaxDynamicSharedMemorySize, SMEM_BYTES);
    lstm_seq_kernel<<<NCTA, NTHR, SMEM_BYTES>>>(
        input, W_ih1, W_hh1, b_ih1, b_hh1,
        W_ih2, W_hh2, b_ih2, b_hh2, W_lin, b_lin, out);
}

// round 13
// speedup vs baseline: 1.0033x; 1.0033x over previous
#include <cuda_runtime.h>

#define Hh 51
#define TT 1024
#define NCTA 128
#define NTHR 640   // threads 0-223 = A (L1 + x-writers + head); 224-639 = B (L2)

// ---- shared memory (float offsets) ----
// sW1 [204][52] W_hh1, col 51 = W_ih1 (x folded); sW2i [204][52] W_ih2 (col51=0);
// sW2h [204][52] W_hh2 (col51=0); sWlin[52]
// sH1/sH2: [2 buf][416] k-pair-tiled: addr(k,b) = (k>>1)*16 + b*2 + (k&1)
//   row 51 of sH1 = x(t+1); row 51 of sH2 = 0.
// OFF_H1 % 32 = 8 ; OFF_H2 - OFF_H1 = 848 (3392B % 128 = 64) -> B ch0/ch1 mixed loads conflict-free
#define OFF_W1   0
#define OFF_W2I  10608
#define OFF_W2H  21216
#define OFF_WLIN 31824
#define OFF_H1   31880
#define OFF_H2   32728
#define SMEM_FLOATS 33576
#define SMEM_BYTES  (SMEM_FLOATS * 4)

typedef unsigned long long u64;

__device__ __forceinline__ void ffma2(u64& d, u64 a, u64 b) {
    asm("fma.rn.f32x2 %0, %1, %2, %0;" : "+l"(d) : "l"(a), "l"(b));
}
__device__ __forceinline__ float2 u2f(u64 v) {
    float2 f;
    asm("mov.b64 {%0, %1}, %2;" : "=f"(f.x), "=f"(f.y) : "l"(v));
    return f;
}
__device__ __forceinline__ u64 f2u(float x, float y) {
    u64 v;
    asm("mov.b64 %0, {%1, %2};" : "=l"(v) : "f"(x), "f"(y));
    return v;
}
__device__ __forceinline__ float sigf(float x) {
    return __fdividef(1.0f, 1.0f + __expf(-x));
}
__device__ __forceinline__ float tanhfast(float x) {
    return 1.0f - __fdividef(2.0f, __expf(2.0f * x) + 1.0f);
}
__device__ __forceinline__ void bar_arrive(int id) {
    asm volatile("bar.arrive %0, %1;" :: "r"(id), "r"(NTHR) : "memory");
}
__device__ __forceinline__ void bar_wait(int id) {
    asm volatile("bar.sync %0, %1;" :: "r"(id), "r"(NTHR) : "memory");
}

// 13 quads, 4 gate rows, batch pair (b0,b1). NO splats: weights consumed as
// packed k-pairs (u64 halves of LDS.128); h tiled so one LDS.128 yields both
// batches' k-pair u64s. a[8] = accs [gate i,f,g,o][b0,b1] of k-even/odd partials.
#define QUADS13(wp0, wp1, wp2, wp3, hb) { \
    _Pragma("unroll") \
    for (int kk = 0; kk < 13; ++kk) { \
        const ulonglong2 wi = *(const ulonglong2*)((wp0) + kk * 4); \
        const ulonglong2 wf = *(const ulonglong2*)((wp1) + kk * 4); \
        const ulonglong2 wg = *(const ulonglong2*)((wp2) + kk * 4); \
        const ulonglong2 wo = *(const ulonglong2*)((wp3) + kk * 4); \
        const ulonglong2 hA = *(const ulonglong2*)((hb) + kk * 32);      /* pair 2kk:   (b0, b1) */ \
        const ulonglong2 hB = *(const ulonglong2*)((hb) + kk * 32 + 16); /* pair 2kk+1: (b0, b1) */ \
        ffma2(a[0], wi.x, hA.x); ffma2(a[0], wi.y, hB.x); \
        ffma2(a[1], wi.x, hA.y); ffma2(a[1], wi.y, hB.y); \
        ffma2(a[2], wf.x, hA.x); ffma2(a[2], wf.y, hB.x); \
        ffma2(a[3], wf.x, hA.y); ffma2(a[3], wf.y, hB.y); \
        ffma2(a[4], wg.x, hA.x); ffma2(a[4], wg.y, hB.x); \
        ffma2(a[5], wg.x, hA.y); ffma2(a[5], wg.y, hB.y); \
        ffma2(a[6], wo.x, hA.x); ffma2(a[6], wo.y, hB.x); \
        ffma2(a[7], wo.x, hA.y); ffma2(a[7], wo.y, hB.y); \
    } }

// fold k-even/odd partials, apply activations, update c, produce h0/h1
#define FOLD_UPDATE(cvar, h0, h1) { \
    float gg_[8]; \
    _Pragma("unroll") \
    for (int i_ = 0; i_ < 8; ++i_) { const float2 t_ = u2f(a[i_]); gg_[i_] = t_.x + t_.y; } \
    { \
        const float iv = sigf(gg_[0]), fv = sigf(gg_[2]); \
        const float gv = tanhfast(gg_[4]), ov = sigf(gg_[6]); \
        cvar.x = fv * cvar.x + iv * gv; \
        h0 = ov * tanhfast(cvar.x); \
    } \
    { \
        const float iv = sigf(gg_[1]), fv = sigf(gg_[3]); \
        const float gv = tanhfast(gg_[5]), ov = sigf(gg_[7]); \
        cvar.y = fv * cvar.y + iv * gv; \
        h1 = ov * tanhfast(cvar.y); \
    } }

__global__ __launch_bounds__(NTHR, 1)
void lstm_seq_kernel(const float* __restrict__ input,
                     const float* __restrict__ W_ih1, const float* __restrict__ W_hh1,
                     const float* __restrict__ b_ih1, const float* __restrict__ b_hh1,
                     const float* __restrict__ W_ih2, const float* __restrict__ W_hh2,
                     const float* __restrict__ b_ih2, const float* __restrict__ b_hh2,
                     const float* __restrict__ W_lin, const float* __restrict__ b_lin,
                     float* __restrict__ out)
{
    extern __shared__ float sm[];
    float* sW1   = sm + OFF_W1;
    float* sW2i  = sm + OFF_W2I;
    float* sW2h  = sm + OFF_W2H;
    float* sWlin = sm + OFF_WLIN;
    float* sH1   = sm + OFF_H1;   // [2][416]
    float* sH2   = sm + OFF_H2;   // [2][416]

    const int tid = threadIdx.x;
    const int b0  = blockIdx.x * 8;

    // ---------------- staging ----------------
    for (int i = tid; i < 204 * Hh; i += NTHR) {
        const int r = i / Hh, k = i % Hh;
        sW1[r * 52 + k]  = W_hh1[i];
        sW2i[r * 52 + k] = W_ih2[i];
        sW2h[r * 52 + k] = W_hh2[i];
    }
    for (int r = tid; r < 204; r += NTHR) {
        sW1[r * 52 + 51]  = W_ih1[r];   // x folded into col 51
        sW2i[r * 52 + 51] = 0.0f;
        sW2h[r * 52 + 51] = 0.0f;
    }
    if (tid < 52) sWlin[tid] = (tid < Hh) ? W_lin[tid] : 0.0f;
    for (int i = tid; i < (OFF_H2 - OFF_H1) + 848; i += NTHR) sH1[i] = 0.0f;
    __syncthreads();   // zeroing before x-staging into h rows
    if (tid < 8) {
        // x(0) -> buf1 row 51 (used by prologue); x(1) -> buf0 row 51 (slot 0)
        sH1[416 + 401 + tid * 2] = input[(b0 + tid) * TT];
        sH1[401 + tid * 2]       = input[(b0 + tid) * TT + 1];
    }

    // ---------------- roles ----------------
    const bool isA = (tid < 224);
    // A gate: tids 0..203 (jA = tid>>2, bp = tid&3); x-writers 204..207; head 208..223
    const int gt  = isA ? tid : (tid - 224);
    const int bp  = gt & 3;
    const int jA  = tid >> 2;                       // A only
    const bool gateA = isA && (jA < Hh);
    // B: (j, bp, ch): bp = gt&3, ch = bit2, jr = gt>>3
    const int chB = (gt >> 2) & 1;
    const int jBr = gt >> 3;
    const bool validB = (jBr < Hh);
    const int jB = validB ? jBr : (Hh - 1);

    const int jrow = isA ? ((jA < Hh) ? jA : (Hh - 1)) : jB;
    const int ri = jrow, rf = Hh + jrow, rg = 2 * Hh + jrow, ro = 3 * Hh + jrow;

    u64 sd[8];
    #pragma unroll
    for (int i = 0; i < 8; ++i) sd[i] = 0;
    const float *wp0, *wp1, *wp2, *wp3;
    if (isA) {
        wp0 = sW1 + ri * 52; wp1 = sW1 + rf * 52;
        wp2 = sW1 + rg * 52; wp3 = sW1 + ro * 52;
        sd[0] = sd[1] = f2u(b_ih1[ri] + b_hh1[ri], 0.0f);
        sd[2] = sd[3] = f2u(b_ih1[rf] + b_hh1[rf], 0.0f);
        sd[4] = sd[5] = f2u(b_ih1[rg] + b_hh1[rg], 0.0f);
        sd[6] = sd[7] = f2u(b_ih1[ro] + b_hh1[ro], 0.0f);
    } else {
        const float* wb = chB ? sW2h : sW2i;
        wp0 = wb + ri * 52; wp1 = wb + rf * 52;
        wp2 = wb + rg * 52; wp3 = wb + ro * 52;
        if (chB == 0) {
            sd[0] = sd[1] = f2u(b_ih2[ri] + b_hh2[ri], 0.0f);
            sd[2] = sd[3] = f2u(b_ih2[rf] + b_hh2[rf], 0.0f);
            sd[4] = sd[5] = f2u(b_ih2[rg] + b_hh2[rg], 0.0f);
            sd[6] = sd[7] = f2u(b_ih2[ro] + b_hh2[ro], 0.0f);
        }
    }
    // store float addrs: h[j][b] at (j>>1)*16 + b*2 + (j&1); this thread: b = 2bp, 2bp+1
    const int sto = (jrow >> 1) * 16 + bp * 4 + (jrow & 1);
    // h read base: + bp*4 (pair-tile column of this batch pair)
    const int hoff = bp * 4;

    // head lanes (tids 208..223): hb = batch, hkq = k half
    const int hl  = tid - 208;
    const int hbb = hl & 7;
    const int hkq = (hl >> 3) & 1;

    float2 cc = make_float2(0.0f, 0.0f);
    const float blin = b_lin[0];

    __syncthreads();

    // ---------------- prologue: A computes h1(0) into buf 0 ----------------
    if (isA) {
        if (gateA) {
            u64 a[8];
            #pragma unroll
            for (int i = 0; i < 8; ++i) a[i] = sd[i];
            const float* hb = sH1 + 416 + hoff;      // buf1: zeros + x(0) at row 51
            QUADS13(wp0, wp1, wp2, wp3, hb)
            float h0, h1;
            FOLD_UPDATE(cc, h0, h1)
            sH1[sto]     = h0;                       // buf0: h1(0)
            sH1[sto + 2] = h1;
        }
        bar_arrive(1);                               // h1(0) ready
    } else {
        bar_arrive(2);
    }

    // ---------------- time loop ----------------
    for (int t = 0; t < TT; ++t) {
        const int pt = t & 1, pn = pt ^ 1;

        if (isA) {
            bar_wait(2);                             // B(t-1) done (buf pn free)
            if (gateA) {
                // h1(t+1) = cell(h1(t)[pt], x(t+1)[row51 of pt]) -> buf pn
                u64 a[8];
                #pragma unroll
                for (int i = 0; i < 8; ++i) a[i] = sd[i];
                const float* hb = sH1 + pt * 416 + hoff;
                QUADS13(wp0, wp1, wp2, wp3, hb)
                float h0, h1;
                FOLD_UPDATE(cc, h0, h1)
                sH1[pn * 416 + sto]     = h0;
                sH1[pn * 416 + sto + 2] = h1;
            } else if (tid < 208) {
                // x-writer: stage x(t+2) into buf pn row 51 (b = 2bp, 2bp+1)
                if (t + 2 < TT) {
                    const int xb = tid - 204;
                    sH1[pn * 416 + 401 + xb * 4]     = input[(b0 + 2 * xb) * TT + t + 2];
                    sH1[pn * 416 + 401 + xb * 4 + 2] = input[(b0 + 2 * xb + 1) * TT + t + 2];
                }
            } else if (t >= 1) {
                // head(t-1): y = W_lin . h2(t-1)[pn] + b
                const float* h2r = sH2 + pn * 416;
                float p = 0.0f;
                #pragma unroll
                for (int s = 0; s < 26; ++s) {
                    const int k = hkq * 26 + s;
                    if (k < Hh)
                        p = fmaf(sWlin[k],
                                 h2r[(k >> 1) * 16 + hbb * 2 + (k & 1)], p);
                }
                p += __shfl_xor_sync(0xFFFF0000u, p, 8);
                if (hkq == 0)
                    out[(b0 + hbb) * TT + (t - 1)] = p + blin;
            }
            bar_arrive(1);                           // h1(t+1) ready
        } else {
            bar_wait(1);                             // h1(t) ready
            // L2 cell(t): ch0 = W_ih2 . h1(t)[pt] (+bias); ch1 = W_hh2 . h2(t-1)[pn]
            u64 a[8];
            #pragma unroll
            for (int i = 0; i < 8; ++i) a[i] = sd[i];
            const float* hb = (chB ? (sH2 + pn * 416) : (sH1 + pt * 416)) + hoff;
            QUADS13(wp0, wp1, wp2, wp3, hb)
            // reduce ch halves across lane^4 pairs (u64 k-partials)
            #pragma unroll
            for (int i = 0; i < 8; ++i) {
                const u64 x_ = __shfl_xor_sync(0xffffffffu, a[i], 4);
                asm("add.rn.f32x2 %0, %0, %1;" : "+l"(a[i]) : "l"(x_));
            }
            float h0, h1;
            FOLD_UPDATE(cc, h0, h1)
            if (validB && chB == 0) {
                sH2[pt * 416 + sto]     = h0;        // h2(t)
                sH2[pt * 416 + sto + 2] = h1;
            }
            bar_arrive(2);
        }
    }

    // ---------------- epilogue: head(TT-1) ----------------
    if (isA) {
        bar_wait(2);
        if (tid >= 208) {
            const float* h2r = sH2 + ((TT - 1) & 1) * 416;
            float p = 0.0f;
            #pragma unroll
            for (int s = 0; s < 26; ++s) {
                const int k = hkq * 26 + s;
                if (k < Hh)
                    p = fmaf(sWlin[k], h2r[(k >> 1) * 16 + hbb * 2 + (k & 1)], p);
            }
            p += __shfl_xor_sync(0xFFFF0000u, p, 8);
            if (hkq == 0)
                out[(b0 + hbb) * TT + (TT - 1)] = p + blin;
        }
    }
}

extern "C" void kernel_launch(void* const* d_in, const int* in_sizes, int n_in,
                              void* d_out, int out_size) {
    const float* input = (const float*)d_in[0];
    const float* W_ih1 = (const float*)d_in[1];
    const float* W_hh1 = (const float*)d_in[2];
    const float* b_ih1 = (const float*)d_in[3];
    const float* b_hh1 = (const float*)d_in[4];
    const float* W_ih2 = (const float*)d_in[5];
    const float* W_hh2 = (const float*)d_in[6];
    const float* b_ih2 = (const float*)d_in[7];
    const float* b_hh2 = (const float*)d_in[8];
    const float* W_lin = (const float*)d_in[9];
    const float* b_lin = (const float*)d_in[10];
    float* out = (float*)d_out;

    cudaFuncSetAttribute(lstm_seq_kernel,
                         cudaFuncAttributeMaxDynamicSharedMemorySize, SMEM_BYTES);
    lstm_seq_kernel<<<NCTA, NTHR, SMEM_BYTES>>>(
        input, W_ih1, W_hh1, b_ih1, b_hh1,
        W_ih2, W_hh2, b_ih2, b_hh2, W_lin, b_lin, out);
}

// round 16
// speedup vs baseline: 1.0294x; 1.0261x over previous
#include <cuda_runtime.h>

#define Hh 51
#define H4 204
#define TT 1024
#define NCTA 128
#define NTHR 672     // warps 0-6: L1 cells; 7-19: L2 half-cells; 20: head

// ---- shared memory (float offsets) ----
// sW1 [204][52] W_hh1; sW2i [204][52] W_ih2; sW2h [204][52] W_hh2 (col 51 = 0)
// sWlin[52]; sX [1024][8] t-major; sH1 [2][52][10]; sH2 [2][52][10]
#define OFF_W1   0
#define OFF_W2I  10608
#define OFF_W2H  21216
#define OFF_WLIN 31824
#define OFF_X    31880
#define OFF_H1   40072   // mod 32 = 8
#define OFF_H2   41112   // mod 32 = 24 -> diff 16: B's h1/h2 dual loads conflict-free
#define SMEM_FLOATS 42152
#define SMEM_BYTES  (SMEM_FLOATS * 4)

typedef unsigned long long u64;

__device__ __forceinline__ u64 splat2(float w) {
    unsigned int wi = __float_as_uint(w);
    u64 r;
    asm("mov.b64 %0, {%1, %1};" : "=l"(r) : "r"(wi));
    return r;
}
__device__ __forceinline__ void ffma2(u64& d, u64 a, u64 b) {
    asm("fma.rn.f32x2 %0, %1, %2, %0;" : "+l"(d) : "l"(a), "l"(b));
}
__device__ __forceinline__ u64 add2(u64 a, u64 b) {
    u64 r;
    asm("add.rn.f32x2 %0, %1, %2;" : "=l"(r) : "l"(a), "l"(b));
    return r;
}
__device__ __forceinline__ float2 u2f(u64 v) {
    float2 f;
    asm("mov.b64 {%0, %1}, %2;" : "=f"(f.x), "=f"(f.y) : "l"(v));
    return f;
}
__device__ __forceinline__ u64 f2u(float x, float y) {
    u64 v;
    asm("mov.b64 %0, {%1, %2};" : "=l"(v) : "f"(x), "f"(y));
    return v;
}
__device__ __forceinline__ float sigf(float x) {
    return __fdividef(1.0f, 1.0f + __expf(-x));
}
__device__ __forceinline__ float tanhfast(float x) {
    return 1.0f - __fdividef(2.0f, __expf(2.0f * x) + 1.0f);
}

// 13 quads (52 k) of 4 gate rows; h rows at stride 10
#define QUADS13(wp0, wp1, wp2, wp3, hrd) { \
    _Pragma("unroll") \
    for (int kk = 0; kk < 13; ++kk) { \
        const float4 wi = *(const float4*)((wp0) + kk * 4); \
        const float4 wf = *(const float4*)((wp1) + kk * 4); \
        const float4 wg = *(const float4*)((wp2) + kk * 4); \
        const float4 wo = *(const float4*)((wp3) + kk * 4); \
        const u64 h0  = *(const u64*)((hrd) + (kk * 4 + 0) * 10); \
        const u64 h1v = *(const u64*)((hrd) + (kk * 4 + 1) * 10); \
        const u64 h2v = *(const u64*)((hrd) + (kk * 4 + 2) * 10); \
        const u64 h3v = *(const u64*)((hrd) + (kk * 4 + 3) * 10); \
        ffma2(ai, splat2(wi.x), h0);  ffma2(ai, splat2(wi.y), h1v); \
        ffma2(ai, splat2(wi.z), h2v); ffma2(ai, splat2(wi.w), h3v); \
        ffma2(af, splat2(wf.x), h0);  ffma2(af, splat2(wf.y), h1v); \
        ffma2(af, splat2(wf.z), h2v); ffma2(af, splat2(wf.w), h3v); \
        ffma2(ag, splat2(wg.x), h0);  ffma2(ag, splat2(wg.y), h1v); \
        ffma2(ag, splat2(wg.z), h2v); ffma2(ag, splat2(wg.w), h3v); \
        ffma2(ao, splat2(wo.x), h0);  ffma2(ao, splat2(wo.y), h1v); \
        ffma2(ao, splat2(wo.z), h2v); ffma2(ao, splat2(wo.w), h3v); \
    } }

#define UPDATE(cvar, hout) { \
    const float2 gi = u2f(ai), gf = u2f(af), gg = u2f(ag), go = u2f(ao); \
    const float i0 = sigf(gi.x), f0 = sigf(gf.x), g0 = tanhfast(gg.x), o0 = sigf(go.x); \
    const float i1 = sigf(gi.y), f1 = sigf(gf.y), g1 = tanhfast(gg.y), o1 = sigf(go.y); \
    cvar.x = f0 * cvar.x + i0 * g0; \
    cvar.y = f1 * cvar.y + i1 * g1; \
    hout = f2u(o0 * tanhfast(cvar.x), o1 * tanhfast(cvar.y)); }

__global__ __launch_bounds__(NTHR, 1)
void lstm_seq_kernel(const float* __restrict__ input,
                     const float* __restrict__ W_ih1, const float* __restrict__ W_hh1,
                     const float* __restrict__ b_ih1, const float* __restrict__ b_hh1,
                     const float* __restrict__ W_ih2, const float* __restrict__ W_hh2,
                     const float* __restrict__ b_ih2, const float* __restrict__ b_hh2,
                     const float* __restrict__ W_lin, const float* __restrict__ b_lin,
                     float* __restrict__ out)
{
    extern __shared__ float sm[];
    float* sW1   = sm + OFF_W1;
    float* sW2i  = sm + OFF_W2I;
    float* sW2h  = sm + OFF_W2H;
    float* sWlin = sm + OFF_WLIN;
    float* sX    = sm + OFF_X;
    float* sH1   = sm + OFF_H1;   // [2][520]
    float* sH2   = sm + OFF_H2;   // [2][520]

    const int tid = threadIdx.x;
    const int b0  = blockIdx.x * 8;

    // ---------------- staging ----------------
    for (int i = tid; i < H4 * Hh; i += NTHR) {
        const int r = i / Hh, k = i % Hh;
        sW1[r * 52 + k]  = W_hh1[i];
        sW2i[r * 52 + k] = W_ih2[i];
        sW2h[r * 52 + k] = W_hh2[i];
    }
    for (int r = tid; r < H4; r += NTHR) {
        sW1[r * 52 + 51]  = 0.0f;
        sW2i[r * 52 + 51] = 0.0f;
        sW2h[r * 52 + 51] = 0.0f;
    }
    if (tid < 52) sWlin[tid] = (tid < Hh) ? W_lin[tid] : 0.0f;
    for (int i = tid; i < 8 * TT; i += NTHR) {
        const int b = i >> 10, t = i & 1023;
        sX[t * 8 + b] = input[b0 * TT + i];
    }
    for (int i = tid; i < 1040; i += NTHR) { sH1[i] = 0.0f; sH2[i] = 0.0f; }

    // ---------------- roles ----------------
    const int wid = tid >> 5;
    const bool isA = (wid < 7);            // L1 cell threads
    const bool isB = (wid >= 7 && wid < 20);
    const float blin = b_lin[0];

    // ----- A config: j = tid>>2 (0..55), bp = tid&3 -----
    const int jA  = tid >> 2;
    const int boA = (tid & 3) * 2;
    const bool actA = isA && (jA < Hh);
    u64 bA_i = 0, bA_f = 0, bA_g = 0, bA_o = 0;
    u64 wxi = 0, wxf = 0, wxg = 0, wxo = 0;
    const float* wA0 = sW1; const float* wA1 = sW1;
    const float* wA2 = sW1; const float* wA3 = sW1;
    if (actA) {
        const int ri = jA, rf = Hh + jA, rg = 2 * Hh + jA, ro = 3 * Hh + jA;
        bA_i = splat2(b_ih1[ri] + b_hh1[ri]);
        bA_f = splat2(b_ih1[rf] + b_hh1[rf]);
        bA_g = splat2(b_ih1[rg] + b_hh1[rg]);
        bA_o = splat2(b_ih1[ro] + b_hh1[ro]);
        wxi = splat2(W_ih1[ri]); wxf = splat2(W_ih1[rf]);
        wxg = splat2(W_ih1[rg]); wxo = splat2(W_ih1[ro]);
        wA0 = sW1 + ri * 52; wA1 = sW1 + rf * 52;
        wA2 = sW1 + rg * 52; wA3 = sW1 + ro * 52;
    }

    // ----- B config: bt = tid-224: bp = bt&3, ch = bit2, j = bt>>3 (clamped) -----
    const int bt  = tid - 224;
    const int boB = (bt & 3) * 2;
    const int chB = (bt >> 2) & 1;
    const int jBr = bt >> 3;
    const bool actB = isB && (jBr < Hh);   // store-enable
    const int jB = (jBr < Hh) ? jBr : (Hh - 1);   // clamp so all lanes run (shuffle convergence)
    u64 sB_i = 0, sB_f = 0, sB_g = 0, sB_o = 0;   // acc seeds: ch0 carries bias
    const float* wB0 = sW2i; const float* wB1 = sW2i;
    const float* wB2 = sW2i; const float* wB3 = sW2i;
    if (isB) {
        const int ri = jB, rf = Hh + jB, rg = 2 * Hh + jB, ro = 3 * Hh + jB;
        if (chB == 0) {
            sB_i = splat2(b_ih2[ri] + b_hh2[ri]);
            sB_f = splat2(b_ih2[rf] + b_hh2[rf]);
            sB_g = splat2(b_ih2[rg] + b_hh2[rg]);
            sB_o = splat2(b_ih2[ro] + b_hh2[ro]);
            wB0 = sW2i + ri * 52; wB1 = sW2i + rf * 52;
            wB2 = sW2i + rg * 52; wB3 = sW2i + ro * 52;
        } else {
            wB0 = sW2h + ri * 52; wB1 = sW2h + rf * 52;
            wB2 = sW2h + rg * 52; wB3 = sW2h + ro * 52;
        }
    }

    // ----- head config (warp 20): b = w&7, kq = w>>3 -----
    const int hw = tid - 640;
    const int hb = hw & 7;
    const int kq = hw >> 3;

    float2 c1 = make_float2(0.0f, 0.0f);
    float2 c2 = make_float2(0.0f, 0.0f);

    __syncthreads();

    // ---------------- prologue: A computes h1(0) into buf 0 ----------------
    if (actA) {
        u64 ai = bA_i, af = bA_f, ag = bA_g, ao = bA_o;
        const u64 xv = *(const u64*)(sX + 0 * 8 + boA);
        ffma2(ai, wxi, xv); ffma2(af, wxf, xv);
        ffma2(ag, wxg, xv); ffma2(ao, wxo, xv);
        const float* hrd = sH1 + 520 + boA;   // buf 1: zeros
        QUADS13(wA0, wA1, wA2, wA3, hrd);
        u64 hnew;
        UPDATE(c1, hnew);
        *(u64*)(sH1 + jA * 10 + boA) = hnew;  // h1(0) -> buf 0
    }
    __syncthreads();

    // ---------------- time loop: ONE barrier per step ----------------
    for (int t = 0; t < TT; ++t) {
        const int pt = t & 1, pn = pt ^ 1;

        if (isA) {
            if (actA && t < TT - 1) {
                // L1 cell for step t+1: reads h1(t)[pt], x(t+1); writes h1(t+1)[pn]
                u64 ai = bA_i, af = bA_f, ag = bA_g, ao = bA_o;
                const u64 xv = *(const u64*)(sX + (t + 1) * 8 + boA);
                ffma2(ai, wxi, xv); ffma2(af, wxf, xv);
                ffma2(ag, wxg, xv); ffma2(ao, wxo, xv);
                const float* hrd = sH1 + pt * 520 + boA;
                QUADS13(wA0, wA1, wA2, wA3, hrd);
                u64 hnew;
                UPDATE(c1, hnew);
                *(u64*)(sH1 + pn * 520 + jA * 10 + boA) = hnew;
            }
        } else if (isB) {
            // L2 cell for step t, split across lane^4 pairs:
            // ch0: ih2 half (reads h1(t)[pt]); ch1: hh2 half (reads h2(t-1)[pn])
            u64 ai = sB_i, af = sB_f, ag = sB_g, ao = sB_o;
            const float* hrd = (chB ? (sH2 + pn * 520) : (sH1 + pt * 520)) + boB;
            QUADS13(wB0, wB1, wB2, wB3, hrd);
            ai = add2(ai, __shfl_xor_sync(0xffffffffu, ai, 4));
            af = add2(af, __shfl_xor_sync(0xffffffffu, af, 4));
            ag = add2(ag, __shfl_xor_sync(0xffffffffu, ag, 4));
            ao = add2(ao, __shfl_xor_sync(0xffffffffu, ao, 4));
            u64 hnew;
            UPDATE(c2, hnew);
            if (actB && chB == 0)
                *(u64*)(sH2 + pt * 520 + jB * 10 + boB) = hnew;   // h2(t)
        } else {
            // head(t-1): y = W_lin . h2(t-1)[pn] + b
            if (t >= 1) {
                const float* h2r = sH2 + pn * 520;
                float p = 0.0f;
                #pragma unroll
                for (int s = 0; s < 13; ++s) {
                    const int k = kq * 13 + s;
                    p = fmaf(sWlin[k], h2r[k * 10 + hb], p);
                }
                p += __shfl_xor_sync(0xffffffffu, p, 8);
                p += __shfl_xor_sync(0xffffffffu, p, 16);
                if (kq == 0)
                    out[(b0 + hb) * TT + (t - 1)] = p + blin;
            }
        }
        __syncthreads();
    }

    // ---------------- epilogue: head(TT-1), h2(TT-1) in buf 1 ----------------
    if (wid == 20) {
        const float* h2r = sH2 + 520;
        float p = 0.0f;
        #pragma unroll
        for (int s = 0; s < 13; ++s) {
            const int k = kq * 13 + s;
            p = fmaf(sWlin[k], h2r[k * 10 + hb], p);
        }
        p += __shfl_xor_sync(0xffffffffu, p, 8);
        p += __shfl_xor_sync(0xffffffffu, p, 16);
        if (kq == 0)
            out[(b0 + hb) * TT + (TT - 1)] = p + blin;
    }
}

extern "C" void kernel_launch(void* const* d_in, const int* in_sizes, int n_in,
                              void* d_out, int out_size) {
    const float* input = (const float*)d_in[0];
    const float* W_ih1 = (const float*)d_in[1];
    const float* W_hh1 = (const float*)d_in[2];
    const float* b_ih1 = (const float*)d_in[3];
    const float* b_hh1 = (const float*)d_in[4];
    const float* W_ih2 = (const float*)d_in[5];
    const float* W_hh2 = (const float*)d_in[6];
    const float* b_ih2 = (const float*)d_in[7];
    const float* b_hh2 = (const float*)d_in[8];
    const float* W_lin = (const float*)d_in[9];
    const float* b_lin = (const float*)d_in[10];
    float* out = (float*)d_out;

    cudaFuncSetAttribute(lstm_seq_kernel,
                         cudaFuncAttributeMaxDynamicSharedMemorySize, SMEM_BYTES);
    lstm_seq_kernel<<<NCTA, NTHR, SMEM_BYTES>>>(
        input, W_ih1, W_hh1, b_ih1, b_hh1,
        W_ih2, W_hh2, b_ih2, b_hh2, W_lin, b_lin, out);
}